// round 6
// baseline (speedup 1.0000x reference)
#include <cuda_runtime.h>
#include <cuda_bf16.h>

// Problem shape (fixed by reference setup_inputs)
#define B 64
#define T 4096
#define H 512

#define OCHUNKS 4            // o-split across blocks in proj

// Scratch (no allocation allowed in kernel_launch)
__device__ float g_vpart[OCHUNKS][B][H];  // partial v per o-chunk
__device__ float g_scores[B * T];         // raw scores [B, T]

// ---------------------------------------------------------------------------
// Kernel 1: partial v: g_vpart[z][b,h] = sum_{o in chunk z} hidden[b,o]*W[o,h]
// Grid: (H/32, B/4, OCHUNKS) = 1024 blocks x 256 threads (8 warps = 8 o-groups
// of 16 o-steps each within the 128-o chunk). BTILE=4 batches per thread.
// ~7 blocks/SM at regs<=32 -> ~85% occ; W L2 traffic = 16MB. No atomics:
// deterministic partials, summed by the scores kernel during sv staging.
// ---------------------------------------------------------------------------
__global__ void __launch_bounds__(256, 8)
proj_hidden_kernel(const float* __restrict__ hidden,
                   const float* __restrict__ W) {
    const int b0 = blockIdx.y * 4;
    const int h0 = blockIdx.x * 32;
    const int oc = blockIdx.z;            // o-chunk, 128 o's
    const int hl = threadIdx.x & 31;      // h lane
    const int og = threadIdx.x >> 5;      // o-group 0..7 (warp-uniform)

    __shared__ float sh[4][128];
    // stage 4 hidden rows x 128 o's: 512 floats / 256 threads -> float2 each
    {
        const int r = threadIdx.x >> 6;           // 0..3
        const int c = threadIdx.x & 63;           // float2 slot 0..63
        reinterpret_cast<float2*>(sh[r])[c] =
            reinterpret_cast<const float2*>(hidden + (size_t)(b0 + r) * H + oc * 128)[c];
    }
    __syncthreads();

    const int obase = oc * 128 + og * 16;
    const float* __restrict__ wp = W + (size_t)obase * H + h0 + hl;
    const int ol = og * 16;
    float acc0 = 0.0f, acc1 = 0.0f, acc2 = 0.0f, acc3 = 0.0f;
#pragma unroll
    for (int o = 0; o < 16; ++o) {
        const float w = wp[(size_t)o * H];
        acc0 += sh[0][ol + o] * w;
        acc1 += sh[1][ol + o] * w;
        acc2 += sh[2][ol + o] * w;
        acc3 += sh[3][ol + o] * w;
    }

    __shared__ float part[8][4][32];
    part[og][0][hl] = acc0;
    part[og][1][hl] = acc1;
    part[og][2][hl] = acc2;
    part[og][3][hl] = acc3;
    __syncthreads();
    if (threadIdx.x < 128) {
        const int bb = threadIdx.x >> 5;   // 0..3
        const int hh = threadIdx.x & 31;
        float r = 0.0f;
#pragma unroll
        for (int g = 0; g < 8; ++g) r += part[g][bb][hh];
        g_vpart[oc][b0 + bb][h0 + hh] = r;
    }
}

// ---------------------------------------------------------------------------
// Kernel 2: scores[b,t] = enc[b,t,:] . v[b,:]
// Grid: (T/64, B). 256 threads = 8 warps; each warp owns 8 t's, processed in
// PAIRS: 8 float4 loads in flight (MLP=8) and the two shuffle-reduce chains
// overlap the next loads. sv staged as the sum of the 4 proj partials.
// __ldcs: enc is a single-use 512MB stream, evict-first.
// ---------------------------------------------------------------------------
__global__ void scores_kernel(const float* __restrict__ enc) {
    const int b    = blockIdx.y;
    const int tile = blockIdx.x;          // 64 t-values per block
    const int tid  = threadIdx.x;         // 256
    const int warp = tid >> 5;
    const int lane = tid & 31;

    __shared__ float sv[H];
    {
        const float2 p0 = reinterpret_cast<const float2*>(g_vpart[0][b])[tid];
        const float2 p1 = reinterpret_cast<const float2*>(g_vpart[1][b])[tid];
        const float2 p2 = reinterpret_cast<const float2*>(g_vpart[2][b])[tid];
        const float2 p3 = reinterpret_cast<const float2*>(g_vpart[3][b])[tid];
        float2 s;
        s.x = (p0.x + p1.x) + (p2.x + p3.x);
        s.y = (p0.y + p1.y) + (p2.y + p3.y);
        reinterpret_cast<float2*>(sv)[tid] = s;
    }
    __syncthreads();

    const float4* __restrict__ vb = reinterpret_cast<const float4*>(sv);
    const float4* __restrict__ base =
        reinterpret_cast<const float4*>(enc + (size_t)b * T * H);

    // cache v in registers (4 float4 per lane)
    float4 w0 = vb[lane], w1 = vb[lane + 32], w2 = vb[lane + 64], w3 = vb[lane + 96];

#pragma unroll
    for (int i = 0; i < 8; i += 2) {
        const int t0 = tile * 64 + warp * 8 + i;
        const float4* __restrict__ rowA = base + (size_t)t0 * (H / 4);
        const float4* __restrict__ rowB = rowA + (H / 4);

        const float4 a0 = __ldcs(rowA + lane);
        const float4 a1 = __ldcs(rowA + lane + 32);
        const float4 a2 = __ldcs(rowA + lane + 64);
        const float4 a3 = __ldcs(rowA + lane + 96);
        const float4 c0 = __ldcs(rowB + lane);
        const float4 c1 = __ldcs(rowB + lane + 32);
        const float4 c2 = __ldcs(rowB + lane + 64);
        const float4 c3 = __ldcs(rowB + lane + 96);

        float accA = a0.x * w0.x + a0.y * w0.y + a0.z * w0.z + a0.w * w0.w;
        accA      += a1.x * w1.x + a1.y * w1.y + a1.z * w1.z + a1.w * w1.w;
        accA      += a2.x * w2.x + a2.y * w2.y + a2.z * w2.z + a2.w * w2.w;
        accA      += a3.x * w3.x + a3.y * w3.y + a3.z * w3.z + a3.w * w3.w;
        float accB = c0.x * w0.x + c0.y * w0.y + c0.z * w0.z + c0.w * w0.w;
        accB      += c1.x * w1.x + c1.y * w1.y + c1.z * w1.z + c1.w * w1.w;
        accB      += c2.x * w2.x + c2.y * w2.y + c2.z * w2.z + c2.w * w2.w;
        accB      += c3.x * w3.x + c3.y * w3.y + c3.z * w3.z + c3.w * w3.w;

#pragma unroll
        for (int off = 16; off; off >>= 1) {
            accA += __shfl_xor_sync(0xffffffffu, accA, off);
            accB += __shfl_xor_sync(0xffffffffu, accB, off);
        }
        if (lane == 0) {
            float2 r; r.x = accA; r.y = accB;
            *reinterpret_cast<float2*>(g_scores + b * T + t0) = r;
        }
    }
}

// ---------------------------------------------------------------------------
// Kernel 3: row softmax over T. One block per b, 1024 threads, float4/thread.
// ---------------------------------------------------------------------------
__global__ void softmax_kernel(float* __restrict__ out) {
    const int b   = blockIdx.x;
    const int tid = threadIdx.x;          // 1024
    const int warp = tid >> 5;
    const int lane = tid & 31;

    const float4 x = reinterpret_cast<const float4*>(g_scores + b * T)[tid];

    __shared__ float red[32];
    __shared__ float sbc;

    // --- block max ---
    float m = fmaxf(fmaxf(x.x, x.y), fmaxf(x.z, x.w));
#pragma unroll
    for (int off = 16; off; off >>= 1)
        m = fmaxf(m, __shfl_xor_sync(0xffffffffu, m, off));
    if (lane == 0) red[warp] = m;
    __syncthreads();
    if (tid < 32) {
        float mm = red[tid];
#pragma unroll
        for (int off = 16; off; off >>= 1)
            mm = fmaxf(mm, __shfl_xor_sync(0xffffffffu, mm, off));
        if (tid == 0) sbc = mm;
    }
    __syncthreads();
    m = sbc;

    // --- exp + block sum ---
    const float e0 = expf(x.x - m);
    const float e1 = expf(x.y - m);
    const float e2 = expf(x.z - m);
    const float e3 = expf(x.w - m);
    float s = (e0 + e1) + (e2 + e3);
#pragma unroll
    for (int off = 16; off; off >>= 1)
        s += __shfl_xor_sync(0xffffffffu, s, off);
    __syncthreads();   // protect red[] reuse
    if (lane == 0) red[warp] = s;
    __syncthreads();
    if (tid < 32) {
        float ss = red[tid];
#pragma unroll
        for (int off = 16; off; off >>= 1)
            ss += __shfl_xor_sync(0xffffffffu, ss, off);
        if (tid == 0) sbc = ss;
    }
    __syncthreads();
    const float inv = 1.0f / sbc;

    float4 y;
    y.x = e0 * inv; y.y = e1 * inv; y.z = e2 * inv; y.w = e3 * inv;
    reinterpret_cast<float4*>(out + b * T)[tid] = y;
}

// ---------------------------------------------------------------------------
extern "C" void kernel_launch(void* const* d_in, const int* in_sizes, int n_in,
                              void* d_out, int out_size) {
    const float* hidden = (const float*)d_in[0];   // [B, H]
    const float* enc    = (const float*)d_in[1];   // [B, T, H]
    const float* W      = (const float*)d_in[2];   // [H, H]
    // d_in[3] = bias: cancels under softmax, unused.
    float* out = (float*)d_out;                    // [B, 1, T]

    {
        dim3 grid(H / 32, B / 4, OCHUNKS);
        proj_hidden_kernel<<<grid, 256>>>(hidden, W);
    }
    {
        dim3 grid(T / 64, B);
        scores_kernel<<<grid, 256>>>(enc);
    }
    softmax_kernel<<<B, 1024>>>(out);
}

// round 7
// speedup vs baseline: 1.0304x; 1.0304x over previous
#include <cuda_runtime.h>
#include <cuda_bf16.h>

// Problem shape (fixed by reference setup_inputs)
#define B 64
#define T 4096
#define H 512

#define OCHUNKS 4            // o-split across blocks in proj

// Scratch (no allocation allowed in kernel_launch)
__device__ float g_vpart[OCHUNKS][B][H];  // partial v per o-chunk
__device__ float g_scores[B * T];         // raw scores [B, T]

// ---------------------------------------------------------------------------
// Kernel 1: partial v: g_vpart[z][b,h] = sum_{o in chunk z} hidden[b,o]*W[o,h]
// Grid: (H/32, B/4, OCHUNKS) = 1024 blocks x 256 threads (8 warps = 8 o-groups
// of 16 o-steps within the 128-o chunk). BTILE=4 batches per thread.
// ~80% occ; W L2 traffic = 16MB. Deterministic partials (no atomics), summed
// by the scores kernel during sv staging.
// ---------------------------------------------------------------------------
__global__ void __launch_bounds__(256, 8)
proj_hidden_kernel(const float* __restrict__ hidden,
                   const float* __restrict__ W) {
    const int b0 = blockIdx.y * 4;
    const int h0 = blockIdx.x * 32;
    const int oc = blockIdx.z;            // o-chunk, 128 o's
    const int hl = threadIdx.x & 31;      // h lane
    const int og = threadIdx.x >> 5;      // o-group 0..7 (warp-uniform)

    __shared__ float sh[4][128];
    // stage 4 hidden rows x 128 o's: 512 floats / 256 threads -> float2 each
    {
        const int r = threadIdx.x >> 6;           // 0..3
        const int c = threadIdx.x & 63;           // float2 slot 0..63
        reinterpret_cast<float2*>(sh[r])[c] =
            reinterpret_cast<const float2*>(hidden + (size_t)(b0 + r) * H + oc * 128)[c];
    }
    __syncthreads();

    const int obase = oc * 128 + og * 16;
    const float* __restrict__ wp = W + (size_t)obase * H + h0 + hl;
    const int ol = og * 16;
    float acc0 = 0.0f, acc1 = 0.0f, acc2 = 0.0f, acc3 = 0.0f;
#pragma unroll
    for (int o = 0; o < 16; ++o) {
        const float w = wp[(size_t)o * H];
        acc0 += sh[0][ol + o] * w;
        acc1 += sh[1][ol + o] * w;
        acc2 += sh[2][ol + o] * w;
        acc3 += sh[3][ol + o] * w;
    }

    __shared__ float part[8][4][32];
    part[og][0][hl] = acc0;
    part[og][1][hl] = acc1;
    part[og][2][hl] = acc2;
    part[og][3][hl] = acc3;
    __syncthreads();
    if (threadIdx.x < 128) {
        const int bb = threadIdx.x >> 5;   // 0..3
        const int hh = threadIdx.x & 31;
        float r = 0.0f;
#pragma unroll
        for (int g = 0; g < 8; ++g) r += part[g][bb][hh];
        g_vpart[oc][b0 + bb][h0 + hh] = r;
    }
}

// ---------------------------------------------------------------------------
// Kernel 2: scores[b,t] = enc[b,t,:] . v[b,:]
// Grid: (T/64, B). 256 threads = 8 warps; each warp owns 8 consecutive t,
// ONE t at a time (MLP_p1=4 — the paired version regressed via cross-CTA
// L1tex queue spread). sv staged as the sum of the 4 proj partials.
// __ldcs: enc is a single-use 512MB stream, evict-first.
// ---------------------------------------------------------------------------
__global__ void scores_kernel(const float* __restrict__ enc) {
    const int b    = blockIdx.y;
    const int tile = blockIdx.x;          // 64 t-values per block
    const int tid  = threadIdx.x;         // 256
    const int warp = tid >> 5;
    const int lane = tid & 31;

    __shared__ float sv[H];
    {
        const float2 p0 = reinterpret_cast<const float2*>(g_vpart[0][b])[tid];
        const float2 p1 = reinterpret_cast<const float2*>(g_vpart[1][b])[tid];
        const float2 p2 = reinterpret_cast<const float2*>(g_vpart[2][b])[tid];
        const float2 p3 = reinterpret_cast<const float2*>(g_vpart[3][b])[tid];
        float2 s;
        s.x = (p0.x + p1.x) + (p2.x + p3.x);
        s.y = (p0.y + p1.y) + (p2.y + p3.y);
        reinterpret_cast<float2*>(sv)[tid] = s;
    }
    __syncthreads();

    const float4* __restrict__ vb = reinterpret_cast<const float4*>(sv);
    const float4* __restrict__ base =
        reinterpret_cast<const float4*>(enc + (size_t)b * T * H);

#pragma unroll
    for (int i = 0; i < 8; ++i) {
        const int t = tile * 64 + warp * 8 + i;
        const float4* __restrict__ row = base + (size_t)t * (H / 4);

        float acc = 0.0f;
#pragma unroll
        for (int k = 0; k < 4; ++k) {
            const float4 x = __ldcs(row + lane + k * 32);
            const float4 w = vb[lane + k * 32];
            acc += x.x * w.x + x.y * w.y + x.z * w.z + x.w * w.w;
        }
#pragma unroll
        for (int off = 16; off; off >>= 1)
            acc += __shfl_xor_sync(0xffffffffu, acc, off);
        if (lane == 0) g_scores[b * T + t] = acc;
    }
}

// ---------------------------------------------------------------------------
// Kernel 3: row softmax over T. One block per b, 1024 threads, float4/thread.
// ---------------------------------------------------------------------------
__global__ void softmax_kernel(float* __restrict__ out) {
    const int b   = blockIdx.x;
    const int tid = threadIdx.x;          // 1024
    const int warp = tid >> 5;
    const int lane = tid & 31;

    const float4 x = reinterpret_cast<const float4*>(g_scores + b * T)[tid];

    __shared__ float red[32];
    __shared__ float sbc;

    // --- block max ---
    float m = fmaxf(fmaxf(x.x, x.y), fmaxf(x.z, x.w));
#pragma unroll
    for (int off = 16; off; off >>= 1)
        m = fmaxf(m, __shfl_xor_sync(0xffffffffu, m, off));
    if (lane == 0) red[warp] = m;
    __syncthreads();
    if (tid < 32) {
        float mm = red[tid];
#pragma unroll
        for (int off = 16; off; off >>= 1)
            mm = fmaxf(mm, __shfl_xor_sync(0xffffffffu, mm, off));
        if (tid == 0) sbc = mm;
    }
    __syncthreads();
    m = sbc;

    // --- exp + block sum ---
    const float e0 = expf(x.x - m);
    const float e1 = expf(x.y - m);
    const float e2 = expf(x.z - m);
    const float e3 = expf(x.w - m);
    float s = (e0 + e1) + (e2 + e3);
#pragma unroll
    for (int off = 16; off; off >>= 1)
        s += __shfl_xor_sync(0xffffffffu, s, off);
    __syncthreads();   // protect red[] reuse
    if (lane == 0) red[warp] = s;
    __syncthreads();
    if (tid < 32) {
        float ss = red[tid];
#pragma unroll
        for (int off = 16; off; off >>= 1)
            ss += __shfl_xor_sync(0xffffffffu, ss, off);
        if (tid == 0) sbc = ss;
    }
    __syncthreads();
    const float inv = 1.0f / sbc;

    float4 y;
    y.x = e0 * inv; y.y = e1 * inv; y.z = e2 * inv; y.w = e3 * inv;
    reinterpret_cast<float4*>(out + b * T)[tid] = y;
}

// ---------------------------------------------------------------------------
extern "C" void kernel_launch(void* const* d_in, const int* in_sizes, int n_in,
                              void* d_out, int out_size) {
    const float* hidden = (const float*)d_in[0];   // [B, H]
    const float* enc    = (const float*)d_in[1];   // [B, T, H]
    const float* W      = (const float*)d_in[2];   // [H, H]
    // d_in[3] = bias: cancels under softmax, unused.
    float* out = (float*)d_out;                    // [B, 1, T]

    {
        dim3 grid(H / 32, B / 4, OCHUNKS);
        proj_hidden_kernel<<<grid, 256>>>(hidden, W);
    }
    {
        dim3 grid(T / 64, B);
        scores_kernel<<<grid, 256>>>(enc);
    }
    softmax_kernel<<<B, 1024>>>(out);
}